// round 12
// baseline (speedup 1.0000x reference)
#include <cuda_runtime.h>
#include <cuda_fp16.h>
#include <cstdint>

#define NNODES 4096
#define NEDGES 131072
#define IN_CH 512
#define E_CH 64
#define HID 256
#define OUTD 16
#define NB_E 5
#define NB_Z 3
#define REWEIGHT 0.6454972243679028f

typedef unsigned long long u64;

__device__ int   g_deg[NNODES];
__device__ int   g_rowptr[NNODES + 1];
__device__ int   g_cursor[NNODES];
__device__ float g_dinv[NNODES];
__device__ int2  g_cw[NEDGES];                         // {col, float_bits(w)}
__device__ __align__(16) __half g_h1[NNODES * HID];    // x@W1 (fp16 gather table)
__device__ __align__(16) __half g_e16[NB_E * NNODES * E_CH];  // e_noise fp16
__device__ float g_we32[E_CH * 32];                    // R * We @ [Wmu|Wsig]
__device__ float g_bewc[32];
__device__ float g_G[E_CH * E_CH];                     // R^2 * We We^T
__device__ float g_v[E_CH];                            // 2R * We @ be
__device__ float g_s0;
__device__ float g_the[NB_E * NNODES * 32];
__device__ float g_thx[NNODES * 32];
__device__ float g_t[NB_E * NNODES * 32];
__device__ float g_acc[8];

#define OFF_ADJ 0ull
#define OFF_MU  (OFF_ADJ + 3ull * NNODES * NNODES)
#define OFF_SIG (OFF_MU  + (u64)NB_E * NNODES * OUTD)
#define OFF_Z   (OFF_SIG + (u64)NB_E * NNODES * OUTD)
#define OFF_ZS  (OFF_Z   + (u64)NB_Z * NNODES * OUTD)
#define OFF_EPS (OFF_ZS  + (u64)NB_Z * NNODES * OUTD)
#define OFF_RK  (OFF_EPS + (u64)NB_Z * NNODES * OUTD)
#define OFF_SNR (OFF_RK + 16ull)

// ---------- f32x2 helpers ----------
__device__ __forceinline__ u64 pack2(float a, float b) {
    u64 r; asm("mov.b64 %0, {%1, %2};" : "=l"(r) : "r"(__float_as_int(a)), "r"(__float_as_int(b))); return r;
}
__device__ __forceinline__ void unpack2f(u64 v, float& a, float& b) {
    int x, y; asm("mov.b64 {%0, %1}, %2;" : "=r"(x), "=r"(y) : "l"(v));
    a = __int_as_float(x); b = __int_as_float(y);
}
__device__ __forceinline__ u64 fma2(u64 a, u64 b, u64 c) {
    u64 d; asm("fma.rn.f32x2 %0, %1, %2, %3;" : "=l"(d) : "l"(a), "l"(b), "l"(c)); return d;
}

// ---------- edge access (inline int64 detection) ----------
__device__ __forceinline__ int detect_w64(const int* __restrict__ ei) {
    return (ei[1] | ei[3] | ei[5] | ei[7] | ei[9] | ei[11] | ei[13] | ei[15]) == 0;
}
__device__ __forceinline__ int edge_src(const int* ei, int i, int w64) { return w64 ? ei[2 * i] : ei[i]; }
__device__ __forceinline__ int edge_dst(const int* ei, int i, int w64) { return w64 ? ei[2 * (NEDGES + i)] : ei[NEDGES + i]; }

// ---------- sgemm body (64x128 tile, BK=16, f32x2) -> g_h1 (fp16) ----------
__device__ __forceinline__ void sgemm_body(const float* __restrict__ A, const float* __restrict__ B,
                                           int K, int bxx, int by, float* pool) {
    float (*As)[65]  = reinterpret_cast<float(*)[65]>(pool);
    float (*Bs)[128] = reinterpret_cast<float(*)[128]>(pool + 16 * 65);
    int tid = threadIdx.x;
    const float* Ab = A + (size_t)by * 64 * K;
    const float* Bb = B + bxx * 128;
    int aRow = tid >> 2, aCol = (tid & 3) * 4;
    int bRow = tid >> 5, bCol = (tid & 31) * 4;
    int ty = tid >> 4, tx = tid & 15;
    u64 acc2[4][4] = {};
    for (int k0 = 0; k0 < K; k0 += 16) {
        float4 a4 = *reinterpret_cast<const float4*>(Ab + (size_t)aRow * K + k0 + aCol);
        float4 b4a = *reinterpret_cast<const float4*>(Bb + (size_t)(k0 + bRow) * HID + bCol);
        float4 b4b = *reinterpret_cast<const float4*>(Bb + (size_t)(k0 + bRow + 8) * HID + bCol);
        __syncthreads();
        As[aCol + 0][aRow] = a4.x; As[aCol + 1][aRow] = a4.y;
        As[aCol + 2][aRow] = a4.z; As[aCol + 3][aRow] = a4.w;
        *reinterpret_cast<float4*>(&Bs[bRow][bCol]) = b4a;
        *reinterpret_cast<float4*>(&Bs[bRow + 8][bCol]) = b4b;
        __syncthreads();
#pragma unroll
        for (int kk = 0; kk < 16; kk++) {
            u64 b2[4];
#pragma unroll
            for (int p = 0; p < 4; p++) b2[p] = reinterpret_cast<const u64*>(&Bs[kk][tx * 8])[p];
#pragma unroll
            for (int i = 0; i < 4; i++) {
                float a = As[kk][ty * 4 + i];
                u64 a2 = pack2(a, a);
#pragma unroll
                for (int p = 0; p < 4; p++) acc2[i][p] = fma2(a2, b2[p], acc2[i][p]);
            }
        }
    }
#pragma unroll
    for (int i = 0; i < 4; i++) {
        size_t row = (size_t)by * 64 + ty * 4 + i;
        int col = bxx * 128 + tx * 8;
        float v[8];
#pragma unroll
        for (int p = 0; p < 4; p++) unpack2f(acc2[i][p], v[2 * p], v[2 * p + 1]);
        __half2 h[4];
#pragma unroll
        for (int p = 0; p < 4; p++) h[p] = __floats2half2_rn(v[2 * p], v[2 * p + 1]);
        uint4 o;
        o.x = *reinterpret_cast<unsigned*>(&h[0]); o.y = *reinterpret_cast<unsigned*>(&h[1]);
        o.z = *reinterpret_cast<unsigned*>(&h[2]); o.w = *reinterpret_cast<unsigned*>(&h[3]);
        *reinterpret_cast<uint4*>(&g_h1[row * HID + col]) = o;
    }
}

// ========== K1: deg_count | we32/bewc | G | v,s0 | e-pack fp16 | sgemm0 ==========
__global__ __launch_bounds__(256) void phase1_kernel(const int* __restrict__ ei,
                                                     const float* __restrict__ x,
                                                     const float* __restrict__ W1,
                                                     const float* __restrict__ e_noise,
                                                     const float* __restrict__ We,
                                                     const float* __restrict__ be,
                                                     const float* __restrict__ Wmu,
                                                     const float* __restrict__ Wsig) {
    __shared__ float pool[16 * 65 + 16 * 128];
    __shared__ float tile[64][33];
    int bx = blockIdx.x, tid = threadIdx.x;
    if (bx < 512) {
        int w64 = detect_w64(ei);
        int i = bx * 256 + tid;
        atomicAdd(&g_deg[edge_dst(ei, i, w64)], 1);
    } else if (bx < 520) {
        int idx = (bx - 512) * 256 + tid;
        int i = idx >> 5, j = idx & 31;
        const float* W = (j < 16) ? Wmu : Wsig;
        int jj = j & 15;
        float acc = 0.0f;
#pragma unroll 8
        for (int k = 0; k < HID; k++) acc = fmaf(We[i * HID + k], W[k * 16 + jj], acc);
        g_we32[i * 32 + j] = acc * REWEIGHT;
    } else if (bx == 520) {
        if (tid < 32) {
            const float* W = (tid < 16) ? Wmu : Wsig;
            int jj = tid & 15;
            float acc = 0.0f;
            for (int k = 0; k < HID; k++) acc = fmaf(be[k], W[k * 16 + jj], acc);
            g_bewc[tid] = acc;
        }
    } else if (bx == 521) {
        float acc[4][4] = {};
        int i0 = (tid >> 4) * 4, j0 = (tid & 15) * 4;
        for (int k0 = 0; k0 < HID; k0 += 32) {
            __syncthreads();
            for (int l = tid; l < 2048; l += 256) {
                int r = l >> 5, kk = l & 31;
                tile[r][kk] = We[r * HID + k0 + kk];
            }
            __syncthreads();
#pragma unroll
            for (int kk = 0; kk < 32; kk++) {
                float a[4], b[4];
#pragma unroll
                for (int ii = 0; ii < 4; ii++) a[ii] = tile[i0 + ii][kk];
#pragma unroll
                for (int jj = 0; jj < 4; jj++) b[jj] = tile[j0 + jj][kk];
#pragma unroll
                for (int ii = 0; ii < 4; ii++)
#pragma unroll
                    for (int jj = 0; jj < 4; jj++) acc[ii][jj] = fmaf(a[ii], b[jj], acc[ii][jj]);
            }
        }
        const float R2 = REWEIGHT * REWEIGHT;
#pragma unroll
        for (int ii = 0; ii < 4; ii++)
#pragma unroll
            for (int jj = 0; jj < 4; jj++) g_G[(i0 + ii) * 64 + j0 + jj] = acc[ii][jj] * R2;
    } else if (bx == 522) {
        if (tid < 64) {
            float a = 0.0f;
            for (int c = 0; c < HID; c++) a = fmaf(We[tid * HID + c], be[c], a);
            g_v[tid] = 2.0f * REWEIGHT * a;
        } else if (tid == 64) {
            float s = 0.0f;
            for (int c = 0; c < HID; c++) s = fmaf(be[c], be[c], s);
            g_s0 = s;
        }
    } else if (bx < 523 + 1280) {
        // pack e_noise -> fp16 (one float4 per thread)
        int i = (bx - 523) * 256 + tid;                 // [0, 327680)
        float4 v = reinterpret_cast<const float4*>(e_noise)[i];
        __half2 h0 = __floats2half2_rn(v.x, v.y);
        __half2 h1 = __floats2half2_rn(v.z, v.w);
        uint2 o;
        o.x = *reinterpret_cast<unsigned*>(&h0);
        o.y = *reinterpret_cast<unsigned*>(&h1);
        reinterpret_cast<uint2*>(g_e16)[i] = o;
    } else {
        int bid = bx - (523 + 1280);
        sgemm_body(x, W1, IN_CH, bid & 1, bid >> 1, pool);
    }
}

// ========== K2: dinv + scan + g_acc zero ==========
__global__ void dinv_scan_kernel() {
    __shared__ int sums[32];
    int tid = threadIdx.x, base = tid * 4;
    if (tid < 8) g_acc[tid] = 0.0f;
    int v[4], s = 0;
#pragma unroll
    for (int i = 0; i < 4; i++) {
        v[i] = g_deg[base + i];
        g_dinv[base + i] = rsqrtf((float)v[i] + 1.0f);
        s += v[i];
    }
    int lane = tid & 31, wid = tid >> 5, ss = s;
#pragma unroll
    for (int o = 1; o < 32; o <<= 1) { int t = __shfl_up_sync(~0u, ss, o); if (lane >= o) ss += t; }
    if (lane == 31) sums[wid] = ss;
    __syncthreads();
    if (wid == 0) {
        int w = sums[lane];
#pragma unroll
        for (int o = 1; o < 32; o <<= 1) { int t = __shfl_up_sync(~0u, w, o); if (lane >= o) w += t; }
        sums[lane] = w;
    }
    __syncthreads();
    int run = ss - s + (wid > 0 ? sums[wid - 1] : 0);
#pragma unroll
    for (int i = 0; i < 4; i++) { g_rowptr[base + i] = run; g_cursor[base + i] = run; run += v[i]; }
    if (tid == 1023) g_rowptr[NNODES] = run;
}

// ========== K3: csr_fill (packed cw) + deg re-zero ==========
__global__ __launch_bounds__(256) void csr_fill_kernel(const int* __restrict__ ei) {
    int i = blockIdx.x * 256 + threadIdx.x;
    int w64 = detect_w64(ei);
    int s = edge_src(ei, i, w64), d = edge_dst(ei, i, w64);
    int pos = atomicAdd(&g_cursor[d], 1);
    int2 cw; cw.x = s; cw.y = __float_as_int(g_dinv[s] * g_dinv[d]);
    g_cw[pos] = cw;
    if (i < NNODES) g_deg[i] = 0;
}

// ========== K4: prop256x(+thx,+sumsq) | propE64(+quad sumsq,+the32) ==========
__global__ __launch_bounds__(256) void phase4_kernel(const float* __restrict__ b1,
                                                     const float* __restrict__ Wmu,
                                                     const float* __restrict__ Wsig) {
    __shared__ float sh[2][256];
    __shared__ float red[2][4][32];
    __shared__ float ws[8];
    __shared__ float shpe[8][64];
    int bx = blockIdx.x, tid = threadIdx.x;
    if (bx < 2048) {
        int g = tid >> 7;
        int n = bx * 2 + g;
        int c2 = tid & 127;
        const __half2* hb = reinterpret_cast<const __half2*>(g_h1);
        int start = g_rowptr[n], end = g_rowptr[n + 1];
        float d = g_dinv[n];
        float2 self = __half22float2(hb[n * 128 + c2]);
        float ax0 = self.x * d * d, ay0 = self.y * d * d;
        float ax1 = 0.0f, ay1 = 0.0f;
        int j = start;
        for (; j + 4 <= end; j += 4) {
            int2 cA = g_cw[j], cB = g_cw[j + 1], cC = g_cw[j + 2], cD = g_cw[j + 3];
            __half2 hA = hb[cA.x * 128 + c2];
            __half2 hB = hb[cB.x * 128 + c2];
            __half2 hC = hb[cC.x * 128 + c2];
            __half2 hD = hb[cD.x * 128 + c2];
            float2 vA = __half22float2(hA), vB = __half22float2(hB);
            float2 vC = __half22float2(hC), vD = __half22float2(hD);
            float wA = __int_as_float(cA.y), wB = __int_as_float(cB.y);
            float wC = __int_as_float(cC.y), wD = __int_as_float(cD.y);
            ax0 = fmaf(wA, vA.x, ax0); ay0 = fmaf(wA, vA.y, ay0);
            ax1 = fmaf(wB, vB.x, ax1); ay1 = fmaf(wB, vB.y, ay1);
            ax0 = fmaf(wC, vC.x, ax0); ay0 = fmaf(wC, vC.y, ay0);
            ax1 = fmaf(wD, vD.x, ax1); ay1 = fmaf(wD, vD.y, ay1);
        }
        for (; j < end; j++) {
            int2 cw = g_cw[j];
            float w = __int_as_float(cw.y);
            float2 v = __half22float2(hb[cw.x * 128 + c2]);
            ax0 = fmaf(w, v.x, ax0); ay0 = fmaf(w, v.y, ay0);
        }
        float2 bb = reinterpret_cast<const float2*>(b1)[c2];
        float ax = fmaxf(ax0 + ax1 + bb.x, 0.0f);
        float ay = fmaxf(ay0 + ay1 + bb.y, 0.0f);
        sh[g][c2 * 2] = ax; sh[g][c2 * 2 + 1] = ay;
        float s = ax * ax + ay * ay;
#pragma unroll
        for (int of = 16; of > 0; of >>= 1) s += __shfl_down_sync(~0u, s, of);
        if ((tid & 31) == 0) ws[tid >> 5] = s;
        __syncthreads();
        if (tid == 0) atomicAdd(&g_acc[0], ws[0] + ws[1] + ws[2] + ws[3]);
        if (tid == 128) atomicAdd(&g_acc[0], ws[4] + ws[5] + ws[6] + ws[7]);
        int seg = (tid >> 5) & 3, c0 = tid & 31;
        const float* W = (c0 < 16) ? Wmu : Wsig;
        int cc = c0 & 15;
        float t = 0.0f;
        int k0 = seg * 64;
#pragma unroll 8
        for (int k = k0; k < k0 + 64; k++) t = fmaf(sh[g][k], W[k * 16 + cc], t);
        red[g][seg][c0] = t;
        __syncthreads();
        if ((tid & 96) == 0)
            g_thx[n * 32 + c0] = red[g][0][c0] + red[g][1][c0] + red[g][2][c0] + red[g][3][c0];
    } else {
        int w = (bx - 2048) * 8 + (tid >> 5);      // (b,n) per warp
        int wg = tid >> 5, lane = tid & 31;
        int b = w >> 12, n = w & (NNODES - 1);
        const __half2* eb = reinterpret_cast<const __half2*>(g_e16);
        int start = g_rowptr[n], end = g_rowptr[n + 1];
        float d = g_dinv[n];
        size_t bb = (size_t)b * NNODES;
        float2 self = __half22float2(eb[(bb + n) * 32 + lane]);
        float px0 = self.x * d * d, py0 = self.y * d * d;
        float px1 = 0.0f, py1 = 0.0f;
        int j = start;
        for (; j + 4 <= end; j += 4) {
            int2 cA = g_cw[j], cB = g_cw[j + 1], cC = g_cw[j + 2], cD = g_cw[j + 3];
            __half2 hA = eb[(bb + cA.x) * 32 + lane];
            __half2 hB = eb[(bb + cB.x) * 32 + lane];
            __half2 hC = eb[(bb + cC.x) * 32 + lane];
            __half2 hD = eb[(bb + cD.x) * 32 + lane];
            float2 vA = __half22float2(hA), vB = __half22float2(hB);
            float2 vC = __half22float2(hC), vD = __half22float2(hD);
            float wA = __int_as_float(cA.y), wB = __int_as_float(cB.y);
            float wC = __int_as_float(cC.y), wD = __int_as_float(cD.y);
            px0 = fmaf(wA, vA.x, px0); py0 = fmaf(wA, vA.y, py0);
            px1 = fmaf(wB, vB.x, px1); py1 = fmaf(wB, vB.y, py1);
            px0 = fmaf(wC, vC.x, px0); py0 = fmaf(wC, vC.y, py0);
            px1 = fmaf(wD, vD.x, px1); py1 = fmaf(wD, vD.y, py1);
        }
        for (; j < end; j++) {
            int2 cw = g_cw[j];
            float wt = __int_as_float(cw.y);
            float2 v = __half22float2(eb[(bb + cw.x) * 32 + lane]);
            px0 = fmaf(wt, v.x, px0); py0 = fmaf(wt, v.y, py0);
        }
        float px = px0 + px1, py = py0 + py1;
        shpe[wg][lane * 2] = px; shpe[wg][lane * 2 + 1] = py;
        __syncwarp();
        float tx = 0.0f, ty = 0.0f;
#pragma unroll 8
        for (int i = 0; i < 64; i++) {
            float a = shpe[wg][i];
            float2 g2 = reinterpret_cast<const float2*>(g_G)[i * 32 + lane];
            tx = fmaf(a, g2.x, tx); ty = fmaf(a, g2.y, ty);
        }
        float2 gv = reinterpret_cast<const float2*>(g_v)[lane];
        float partial = (tx + gv.x) * px + (ty + gv.y) * py;
#pragma unroll
        for (int of = 16; of > 0; of >>= 1) partial += __shfl_down_sync(~0u, partial, of);
        if (lane == 0) atomicAdd(&g_acc[1 + b], partial + g_s0);
        float a32 = 0.0f;
#pragma unroll 8
        for (int k = 0; k < 64; k++)
            a32 = fmaf(shpe[wg][k], g_we32[k * 32 + lane], a32);
        g_the[(size_t)w * 32 + lane] = a32;
    }
}

// ========== K5: t = thx + the + bewc (elementwise) ==========
__global__ void tassemble_kernel() {
    int i = blockIdx.x * 1024 + threadIdx.x;
    int row = i >> 5, c = i & 31;
    int n = row & (NNODES - 1);
    g_t[i] = g_thx[n * 32 + c] + g_the[i] + g_bewc[c];
}

// ========== K6: mu/sig = P(t) + bias, fused z ==========
__global__ void prop32z_kernel(const float* __restrict__ bmu, const float* __restrict__ bsig,
                               const float* __restrict__ eps, float* __restrict__ out) {
    int warp = (blockIdx.x * blockDim.x + threadIdx.x) >> 5;
    int lane = threadIdx.x & 31;
    int b = warp >> 12, n = warp & (NNODES - 1);
    const float* tb = g_t + (size_t)b * NNODES * 32;
    float d = g_dinv[n];
    float acc0 = tb[(size_t)n * 32 + lane] * d * d;
    float acc1 = 0.0f;
    int start = g_rowptr[n], end = g_rowptr[n + 1];
    int j = start;
    for (; j + 4 <= end; j += 4) {
        int2 cA = g_cw[j], cB = g_cw[j + 1], cC = g_cw[j + 2], cD = g_cw[j + 3];
        float vA = tb[(size_t)cA.x * 32 + lane];
        float vB = tb[(size_t)cB.x * 32 + lane];
        float vC = tb[(size_t)cC.x * 32 + lane];
        float vD = tb[(size_t)cD.x * 32 + lane];
        acc0 = fmaf(__int_as_float(cA.y), vA, acc0);
        acc1 = fmaf(__int_as_float(cB.y), vB, acc1);
        acc0 = fmaf(__int_as_float(cC.y), vC, acc0);
        acc1 = fmaf(__int_as_float(cD.y), vD, acc1);
    }
    for (; j < end; j++) {
        int2 cw = g_cw[j];
        acc0 = fmaf(__int_as_float(cw.y), tb[(size_t)cw.x * 32 + lane], acc0);
    }
    float acc = acc0 + acc1;
    float biased = acc + ((lane < 16) ? bmu[lane] : bsig[lane - 16]);
    size_t base = ((size_t)b * NNODES + n) * OUTD;
    if (lane < 16) out[OFF_MU + base + lane] = biased;
    else           out[OFF_SIG + base + (lane - 16)] = biased;
    if (b >= 2) {
        float sig = __shfl_sync(~0u, biased, lane + 16);
        if (lane < 16) {
            size_t zi = ((size_t)(b - 2) * NNODES + n) * OUTD + lane;
            float e = eps[zi];
            float zv = fmaf(e, __expf(0.5f * sig), biased);
            out[OFF_Z + zi] = zv;
            out[OFF_ZS + zi] = zv;
            out[OFF_EPS + zi] = e;
        }
    }
}

// ========== K7: adj = sigmoid(z z^T) + snr/rk tail ==========
__device__ __forceinline__ float sigmoid1(float x) {
    float e = __expf(-x);
    float d = 1.0f + e;
    float r; asm("rcp.approx.f32 %0, %1;" : "=f"(r) : "f"(d));
    return r;
}

__global__ __launch_bounds__(256) void adj_kernel(const float* __restrict__ rk_lgt,
                                                  float* __restrict__ out) {
    int tid = threadIdx.x;
    if (blockIdx.x == 0 && blockIdx.y == 0 && blockIdx.z == 0 && tid < 32) {
        if (tid < 5) out[OFF_SNR + tid] = g_acc[0] / g_acc[1 + tid];
        if (tid < 16) out[OFF_RK + tid] = sqrtf(1.0f / (1.0f + expf(-rk_lgt[tid])));
    }
    const float* zb = out + OFF_Z + (size_t)blockIdx.z * NNODES * OUTD;
    float* ab = out + OFF_ADJ + (size_t)blockIdx.z * NNODES * NNODES;
    __shared__ float ziT[16][132];
    __shared__ float zjT[16][132];
    int i0 = blockIdx.y * 128, j0 = blockIdx.x * 128;
#pragma unroll
    for (int rnd = 0; rnd < 2; rnd++) {
        int L4 = tid + rnd * 256;
        float4 a = *reinterpret_cast<const float4*>(zb + (size_t)i0 * 16 + L4 * 4);
        float4 b = *reinterpret_cast<const float4*>(zb + (size_t)j0 * 16 + L4 * 4);
        int r = L4 >> 2, k0 = (L4 & 3) * 4;
        ziT[k0 + 0][r] = a.x; ziT[k0 + 1][r] = a.y; ziT[k0 + 2][r] = a.z; ziT[k0 + 3][r] = a.w;
        zjT[k0 + 0][r] = b.x; zjT[k0 + 1][r] = b.y; zjT[k0 + 2][r] = b.z; zjT[k0 + 3][r] = b.w;
    }
    __syncthreads();
    int tx = tid & 15, ty = tid >> 4;
    u64 acc2[8][4] = {};
#pragma unroll
    for (int k = 0; k < 16; k++) {
        float4 b0 = *reinterpret_cast<const float4*>(&zjT[k][tx * 8]);
        float4 b1 = *reinterpret_cast<const float4*>(&zjT[k][tx * 8 + 4]);
        u64 b2[4];
        b2[0] = pack2(b0.x, b0.y); b2[1] = pack2(b0.z, b0.w);
        b2[2] = pack2(b1.x, b1.y); b2[3] = pack2(b1.z, b1.w);
        float4 a0 = *reinterpret_cast<const float4*>(&ziT[k][ty * 8]);
        float4 a1 = *reinterpret_cast<const float4*>(&ziT[k][ty * 8 + 4]);
        float av[8] = {a0.x, a0.y, a0.z, a0.w, a1.x, a1.y, a1.z, a1.w};
#pragma unroll
        for (int i = 0; i < 8; i++) {
            u64 a2 = pack2(av[i], av[i]);
#pragma unroll
            for (int p = 0; p < 4; p++) acc2[i][p] = fma2(a2, b2[p], acc2[i][p]);
        }
    }
#pragma unroll
    for (int i = 0; i < 8; i++) {
        float v[8];
#pragma unroll
        for (int p = 0; p < 4; p++) unpack2f(acc2[i][p], v[2 * p], v[2 * p + 1]);
        float4 o0, o1;
        o0.x = sigmoid1(v[0]); o0.y = sigmoid1(v[1]); o0.z = sigmoid1(v[2]); o0.w = sigmoid1(v[3]);
        o1.x = sigmoid1(v[4]); o1.y = sigmoid1(v[5]); o1.z = sigmoid1(v[6]); o1.w = sigmoid1(v[7]);
        float* row = ab + (size_t)(i0 + ty * 8 + i) * NNODES + j0 + tx * 8;
        *reinterpret_cast<float4*>(row) = o0;
        *reinterpret_cast<float4*>(row + 4) = o1;
    }
}

// =================================================================================
extern "C" void kernel_launch(void* const* d_in, const int* in_sizes, int n_in,
                              void* d_out, int out_size) {
    (void)in_sizes; (void)n_in; (void)out_size;
    const float* x       = (const float*)d_in[0];
    const int*   ei      = (const int*)d_in[1];
    const float* e_noise = (const float*)d_in[2];
    const float* eps     = (const float*)d_in[3];
    const float* W1      = (const float*)d_in[4];
    const float* b1      = (const float*)d_in[5];
    const float* We      = (const float*)d_in[6];
    const float* be      = (const float*)d_in[7];
    const float* Wmu     = (const float*)d_in[8];
    const float* bmu     = (const float*)d_in[9];
    const float* Wsig    = (const float*)d_in[10];
    const float* bsig    = (const float*)d_in[11];
    const float* rk_lgt  = (const float*)d_in[12];
    float* out = (float*)d_out;

    phase1_kernel<<<523 + 1280 + 128, 256>>>(ei, x, W1, e_noise, We, be, Wmu, Wsig);
    dinv_scan_kernel<<<1, 1024>>>();
    csr_fill_kernel<<<512, 256>>>(ei);
    phase4_kernel<<<2048 + 2560, 256>>>(b1, Wmu, Wsig);
    tassemble_kernel<<<NB_E * NNODES * 32 / 1024, 1024>>>();
    prop32z_kernel<<<2560, 256>>>(bmu, bsig, eps, out);
    adj_kernel<<<dim3(32, 32, NB_Z), 256>>>(rk_lgt, out);
}

// round 13
// speedup vs baseline: 1.1724x; 1.1724x over previous
#include <cuda_runtime.h>
#include <cuda_fp16.h>
#include <cstdint>

#define NNODES 4096
#define NEDGES 131072
#define IN_CH 512
#define E_CH 64
#define HID 256
#define OUTD 16
#define NB_E 5
#define NB_Z 3
#define REWEIGHT 0.6454972243679028f

typedef unsigned long long u64;

__device__ int   g_deg[NNODES];
__device__ int   g_rowptr[NNODES + 1];
__device__ int   g_cursor[NNODES];
__device__ float g_dinv[NNODES];
__device__ int2  g_cw[NEDGES];                         // {col, float_bits(w)}
__device__ __align__(16) __half g_h1[NNODES * HID];    // x@W1 (fp16 gather table)
__device__ __align__(16) __half g_e16[NB_E * NNODES * E_CH];  // e_noise fp16
__device__ float g_we32[E_CH * 32];                    // R * We @ [Wmu|Wsig]
__device__ float g_bewc[32];
__device__ float g_G[E_CH * E_CH];                     // R^2 * We We^T
__device__ float g_v[E_CH];                            // 2R * We @ be
__device__ float g_s0;
__device__ float g_the[NB_E * NNODES * 32];
__device__ float g_thx[NNODES * 32];
__device__ float g_t[NB_E * NNODES * 32];
__device__ float g_acc[8];

#define OFF_ADJ 0ull
#define OFF_MU  (OFF_ADJ + 3ull * NNODES * NNODES)
#define OFF_SIG (OFF_MU  + (u64)NB_E * NNODES * OUTD)
#define OFF_Z   (OFF_SIG + (u64)NB_E * NNODES * OUTD)
#define OFF_ZS  (OFF_Z   + (u64)NB_Z * NNODES * OUTD)
#define OFF_EPS (OFF_ZS  + (u64)NB_Z * NNODES * OUTD)
#define OFF_RK  (OFF_EPS + (u64)NB_Z * NNODES * OUTD)
#define OFF_SNR (OFF_RK + 16ull)

// ---------- f32x2 helpers ----------
__device__ __forceinline__ u64 pack2(float a, float b) {
    u64 r; asm("mov.b64 %0, {%1, %2};" : "=l"(r) : "r"(__float_as_int(a)), "r"(__float_as_int(b))); return r;
}
__device__ __forceinline__ void unpack2f(u64 v, float& a, float& b) {
    int x, y; asm("mov.b64 {%0, %1}, %2;" : "=r"(x), "=r"(y) : "l"(v));
    a = __int_as_float(x); b = __int_as_float(y);
}
__device__ __forceinline__ u64 fma2(u64 a, u64 b, u64 c) {
    u64 d; asm("fma.rn.f32x2 %0, %1, %2, %3;" : "=l"(d) : "l"(a), "l"(b), "l"(c)); return d;
}
__device__ __forceinline__ float4 h4_to_f4(uint2 u) {
    __half2 a = *reinterpret_cast<__half2*>(&u.x);
    __half2 b = *reinterpret_cast<__half2*>(&u.y);
    float2 fa = __half22float2(a), fb = __half22float2(b);
    float4 r; r.x = fa.x; r.y = fa.y; r.z = fb.x; r.w = fb.y; return r;
}

// ---------- edge access (inline int64 detection) ----------
__device__ __forceinline__ int detect_w64(const int* __restrict__ ei) {
    return (ei[1] | ei[3] | ei[5] | ei[7] | ei[9] | ei[11] | ei[13] | ei[15]) == 0;
}
__device__ __forceinline__ int edge_src(const int* ei, int i, int w64) { return w64 ? ei[2 * i] : ei[i]; }
__device__ __forceinline__ int edge_dst(const int* ei, int i, int w64) { return w64 ? ei[2 * (NEDGES + i)] : ei[NEDGES + i]; }

// ---------- sgemm body (64x128 tile, BK=16, f32x2) -> g_h1 (fp16) ----------
__device__ __forceinline__ void sgemm_body(const float* __restrict__ A, const float* __restrict__ B,
                                           int K, int bxx, int by, float* pool) {
    float (*As)[65]  = reinterpret_cast<float(*)[65]>(pool);
    float (*Bs)[128] = reinterpret_cast<float(*)[128]>(pool + 16 * 65);
    int tid = threadIdx.x;
    const float* Ab = A + (size_t)by * 64 * K;
    const float* Bb = B + bxx * 128;
    int aRow = tid >> 2, aCol = (tid & 3) * 4;
    int bRow = tid >> 5, bCol = (tid & 31) * 4;
    int ty = tid >> 4, tx = tid & 15;
    u64 acc2[4][4] = {};
    for (int k0 = 0; k0 < K; k0 += 16) {
        float4 a4 = *reinterpret_cast<const float4*>(Ab + (size_t)aRow * K + k0 + aCol);
        float4 b4a = *reinterpret_cast<const float4*>(Bb + (size_t)(k0 + bRow) * HID + bCol);
        float4 b4b = *reinterpret_cast<const float4*>(Bb + (size_t)(k0 + bRow + 8) * HID + bCol);
        __syncthreads();
        As[aCol + 0][aRow] = a4.x; As[aCol + 1][aRow] = a4.y;
        As[aCol + 2][aRow] = a4.z; As[aCol + 3][aRow] = a4.w;
        *reinterpret_cast<float4*>(&Bs[bRow][bCol]) = b4a;
        *reinterpret_cast<float4*>(&Bs[bRow + 8][bCol]) = b4b;
        __syncthreads();
#pragma unroll
        for (int kk = 0; kk < 16; kk++) {
            u64 b2[4];
#pragma unroll
            for (int p = 0; p < 4; p++) b2[p] = reinterpret_cast<const u64*>(&Bs[kk][tx * 8])[p];
#pragma unroll
            for (int i = 0; i < 4; i++) {
                float a = As[kk][ty * 4 + i];
                u64 a2 = pack2(a, a);
#pragma unroll
                for (int p = 0; p < 4; p++) acc2[i][p] = fma2(a2, b2[p], acc2[i][p]);
            }
        }
    }
#pragma unroll
    for (int i = 0; i < 4; i++) {
        size_t row = (size_t)by * 64 + ty * 4 + i;
        int col = bxx * 128 + tx * 8;
        float v[8];
#pragma unroll
        for (int p = 0; p < 4; p++) unpack2f(acc2[i][p], v[2 * p], v[2 * p + 1]);
        __half2 h[4];
#pragma unroll
        for (int p = 0; p < 4; p++) h[p] = __floats2half2_rn(v[2 * p], v[2 * p + 1]);
        uint4 o;
        o.x = *reinterpret_cast<unsigned*>(&h[0]); o.y = *reinterpret_cast<unsigned*>(&h[1]);
        o.z = *reinterpret_cast<unsigned*>(&h[2]); o.w = *reinterpret_cast<unsigned*>(&h[3]);
        *reinterpret_cast<uint4*>(&g_h1[row * HID + col]) = o;
    }
}

// ========== K1: sgemm0 FIRST | deg_count | we32/bewc | G | v,s0 | e-pack ==========
__global__ __launch_bounds__(256) void phase1_kernel(const int* __restrict__ ei,
                                                     const float* __restrict__ x,
                                                     const float* __restrict__ W1,
                                                     const float* __restrict__ e_noise,
                                                     const float* __restrict__ We,
                                                     const float* __restrict__ be,
                                                     const float* __restrict__ Wmu,
                                                     const float* __restrict__ Wsig) {
    __shared__ float pool[16 * 65 + 16 * 128];
    __shared__ float tile[64][33];
    int bx = blockIdx.x, tid = threadIdx.x;
    if (bx < 128) {
        sgemm_body(x, W1, IN_CH, bx & 1, bx >> 1, pool);
    } else if (bx < 640) {
        int w64 = detect_w64(ei);
        int i = (bx - 128) * 256 + tid;
        atomicAdd(&g_deg[edge_dst(ei, i, w64)], 1);
    } else if (bx < 648) {
        int idx = (bx - 640) * 256 + tid;
        int i = idx >> 5, j = idx & 31;
        const float* W = (j < 16) ? Wmu : Wsig;
        int jj = j & 15;
        float acc = 0.0f;
#pragma unroll 8
        for (int k = 0; k < HID; k++) acc = fmaf(We[i * HID + k], W[k * 16 + jj], acc);
        g_we32[i * 32 + j] = acc * REWEIGHT;
    } else if (bx == 648) {
        if (tid < 32) {
            const float* W = (tid < 16) ? Wmu : Wsig;
            int jj = tid & 15;
            float acc = 0.0f;
            for (int k = 0; k < HID; k++) acc = fmaf(be[k], W[k * 16 + jj], acc);
            g_bewc[tid] = acc;
        }
    } else if (bx == 649) {
        float acc[4][4] = {};
        int i0 = (tid >> 4) * 4, j0 = (tid & 15) * 4;
        for (int k0 = 0; k0 < HID; k0 += 32) {
            __syncthreads();
            for (int l = tid; l < 2048; l += 256) {
                int r = l >> 5, kk = l & 31;
                tile[r][kk] = We[r * HID + k0 + kk];
            }
            __syncthreads();
#pragma unroll
            for (int kk = 0; kk < 32; kk++) {
                float a[4], b[4];
#pragma unroll
                for (int ii = 0; ii < 4; ii++) a[ii] = tile[i0 + ii][kk];
#pragma unroll
                for (int jj = 0; jj < 4; jj++) b[jj] = tile[j0 + jj][kk];
#pragma unroll
                for (int ii = 0; ii < 4; ii++)
#pragma unroll
                    for (int jj = 0; jj < 4; jj++) acc[ii][jj] = fmaf(a[ii], b[jj], acc[ii][jj]);
            }
        }
        const float R2 = REWEIGHT * REWEIGHT;
#pragma unroll
        for (int ii = 0; ii < 4; ii++)
#pragma unroll
            for (int jj = 0; jj < 4; jj++) g_G[(i0 + ii) * 64 + j0 + jj] = acc[ii][jj] * R2;
    } else if (bx == 650) {
        if (tid < 64) {
            float a = 0.0f;
            for (int c = 0; c < HID; c++) a = fmaf(We[tid * HID + c], be[c], a);
            g_v[tid] = 2.0f * REWEIGHT * a;
        } else if (tid == 64) {
            float s = 0.0f;
            for (int c = 0; c < HID; c++) s = fmaf(be[c], be[c], s);
            g_s0 = s;
        }
    } else {
        // pack e_noise -> fp16 (one float4 per thread)
        int i = (bx - 651) * 256 + tid;                 // [0, 327680)
        float4 v = reinterpret_cast<const float4*>(e_noise)[i];
        __half2 h0 = __floats2half2_rn(v.x, v.y);
        __half2 h1 = __floats2half2_rn(v.z, v.w);
        uint2 o;
        o.x = *reinterpret_cast<unsigned*>(&h0);
        o.y = *reinterpret_cast<unsigned*>(&h1);
        reinterpret_cast<uint2*>(g_e16)[i] = o;
    }
}

// ========== K2: dinv + scan + g_acc zero ==========
__global__ void dinv_scan_kernel() {
    __shared__ int sums[32];
    int tid = threadIdx.x, base = tid * 4;
    if (tid < 8) g_acc[tid] = 0.0f;
    int v[4], s = 0;
#pragma unroll
    for (int i = 0; i < 4; i++) {
        v[i] = g_deg[base + i];
        g_dinv[base + i] = rsqrtf((float)v[i] + 1.0f);
        s += v[i];
    }
    int lane = tid & 31, wid = tid >> 5, ss = s;
#pragma unroll
    for (int o = 1; o < 32; o <<= 1) { int t = __shfl_up_sync(~0u, ss, o); if (lane >= o) ss += t; }
    if (lane == 31) sums[wid] = ss;
    __syncthreads();
    if (wid == 0) {
        int w = sums[lane];
#pragma unroll
        for (int o = 1; o < 32; o <<= 1) { int t = __shfl_up_sync(~0u, w, o); if (lane >= o) w += t; }
        sums[lane] = w;
    }
    __syncthreads();
    int run = ss - s + (wid > 0 ? sums[wid - 1] : 0);
#pragma unroll
    for (int i = 0; i < 4; i++) { g_rowptr[base + i] = run; g_cursor[base + i] = run; run += v[i]; }
    if (tid == 1023) g_rowptr[NNODES] = run;
}

// ========== K3: csr_fill (packed cw) + deg re-zero ==========
__global__ __launch_bounds__(256) void csr_fill_kernel(const int* __restrict__ ei) {
    int i = blockIdx.x * 256 + threadIdx.x;
    int w64 = detect_w64(ei);
    int s = edge_src(ei, i, w64), d = edge_dst(ei, i, w64);
    int pos = atomicAdd(&g_cursor[d], 1);
    int2 cw; cw.x = s; cw.y = __float_as_int(g_dinv[s] * g_dinv[d]);
    g_cw[pos] = cw;
    if (i < NNODES) g_deg[i] = 0;
}

// ========== K4: prop256x 4ch/thread (+thx,+sumsq) | propE64(+quad,+the32) ==========
__global__ __launch_bounds__(256) void phase4_kernel(const float* __restrict__ b1,
                                                     const float* __restrict__ Wmu,
                                                     const float* __restrict__ Wsig) {
    __shared__ float sh[4][256];
    __shared__ float red[4][2][32];
    __shared__ float ws[8];
    __shared__ float shpe[8][64];
    int bx = blockIdx.x, tid = threadIdx.x;
    if (bx < 1024) {
        int g = tid >> 6;                  // node within block (0..3)
        int t = tid & 63;                  // channel-quad id (4 ch per thread)
        int n = bx * 4 + g;
        const uint2* hb = reinterpret_cast<const uint2*>(g_h1);  // 64 uint2 per row
        int start = g_rowptr[n], end = g_rowptr[n + 1];
        float d = g_dinv[n];
        float4 sv = h4_to_f4(hb[n * 64 + t]);
        float a0 = sv.x * d * d, a1 = sv.y * d * d, a2 = sv.z * d * d, a3 = sv.w * d * d;
        float b0 = 0.0f, b1r = 0.0f, b2 = 0.0f, b3 = 0.0f;
        int j = start;
        for (; j + 4 <= end; j += 4) {
            int2 cA = g_cw[j], cB = g_cw[j + 1], cC = g_cw[j + 2], cD = g_cw[j + 3];
            uint2 uA = hb[cA.x * 64 + t];
            uint2 uB = hb[cB.x * 64 + t];
            uint2 uC = hb[cC.x * 64 + t];
            uint2 uD = hb[cD.x * 64 + t];
            float4 vA = h4_to_f4(uA), vB = h4_to_f4(uB), vC = h4_to_f4(uC), vD = h4_to_f4(uD);
            float wA = __int_as_float(cA.y), wB = __int_as_float(cB.y);
            float wC = __int_as_float(cC.y), wD = __int_as_float(cD.y);
            a0 = fmaf(wA, vA.x, a0); a1 = fmaf(wA, vA.y, a1); a2 = fmaf(wA, vA.z, a2); a3 = fmaf(wA, vA.w, a3);
            b0 = fmaf(wB, vB.x, b0); b1r = fmaf(wB, vB.y, b1r); b2 = fmaf(wB, vB.z, b2); b3 = fmaf(wB, vB.w, b3);
            a0 = fmaf(wC, vC.x, a0); a1 = fmaf(wC, vC.y, a1); a2 = fmaf(wC, vC.z, a2); a3 = fmaf(wC, vC.w, a3);
            b0 = fmaf(wD, vD.x, b0); b1r = fmaf(wD, vD.y, b1r); b2 = fmaf(wD, vD.z, b2); b3 = fmaf(wD, vD.w, b3);
        }
        for (; j < end; j++) {
            int2 cw = g_cw[j];
            float w = __int_as_float(cw.y);
            float4 v = h4_to_f4(hb[cw.x * 64 + t]);
            a0 = fmaf(w, v.x, a0); a1 = fmaf(w, v.y, a1); a2 = fmaf(w, v.z, a2); a3 = fmaf(w, v.w, a3);
        }
        float4 bb = reinterpret_cast<const float4*>(b1)[t];
        float4 hv;
        hv.x = fmaxf(a0 + b0 + bb.x, 0.0f);
        hv.y = fmaxf(a1 + b1r + bb.y, 0.0f);
        hv.z = fmaxf(a2 + b2 + bb.z, 0.0f);
        hv.w = fmaxf(a3 + b3 + bb.w, 0.0f);
        reinterpret_cast<float4*>(sh[g])[t] = hv;
        float s = hv.x * hv.x + hv.y * hv.y + hv.z * hv.z + hv.w * hv.w;
#pragma unroll
        for (int of = 16; of > 0; of >>= 1) s += __shfl_down_sync(~0u, s, of);
        if ((tid & 31) == 0) ws[tid >> 5] = s;
        __syncthreads();
        if (tid == 0) {
            float tot = ws[0] + ws[1] + ws[2] + ws[3] + ws[4] + ws[5] + ws[6] + ws[7];
            atomicAdd(&g_acc[0], tot);
        }
        // thx = hx_row @ [Wmu|Wsig]  (2 segments of 128 k per node)
        int seg = t >> 5, c0 = t & 31;
        const float* W = (c0 < 16) ? Wmu : Wsig;
        int cc = c0 & 15;
        float tt = 0.0f;
        int k0 = seg * 128;
#pragma unroll 16
        for (int k = k0; k < k0 + 128; k++) tt = fmaf(sh[g][k], W[k * 16 + cc], tt);
        red[g][seg][c0] = tt;
        __syncthreads();
        if (t < 32) g_thx[n * 32 + t] = red[g][0][t] + red[g][1][t];
    } else {
        int w = (bx - 1024) * 8 + (tid >> 5);      // (b,n) per warp
        int wg = tid >> 5, lane = tid & 31;
        int b = w >> 12, n = w & (NNODES - 1);
        const __half2* eb = reinterpret_cast<const __half2*>(g_e16);
        int start = g_rowptr[n], end = g_rowptr[n + 1];
        float d = g_dinv[n];
        size_t bb = (size_t)b * NNODES;
        float2 self = __half22float2(eb[(bb + n) * 32 + lane]);
        float px0 = self.x * d * d, py0 = self.y * d * d;
        float px1 = 0.0f, py1 = 0.0f;
        int j = start;
        for (; j + 4 <= end; j += 4) {
            int2 cA = g_cw[j], cB = g_cw[j + 1], cC = g_cw[j + 2], cD = g_cw[j + 3];
            __half2 hA = eb[(bb + cA.x) * 32 + lane];
            __half2 hB = eb[(bb + cB.x) * 32 + lane];
            __half2 hC = eb[(bb + cC.x) * 32 + lane];
            __half2 hD = eb[(bb + cD.x) * 32 + lane];
            float2 vA = __half22float2(hA), vB = __half22float2(hB);
            float2 vC = __half22float2(hC), vD = __half22float2(hD);
            float wA = __int_as_float(cA.y), wB = __int_as_float(cB.y);
            float wC = __int_as_float(cC.y), wD = __int_as_float(cD.y);
            px0 = fmaf(wA, vA.x, px0); py0 = fmaf(wA, vA.y, py0);
            px1 = fmaf(wB, vB.x, px1); py1 = fmaf(wB, vB.y, py1);
            px0 = fmaf(wC, vC.x, px0); py0 = fmaf(wC, vC.y, py0);
            px1 = fmaf(wD, vD.x, px1); py1 = fmaf(wD, vD.y, py1);
        }
        for (; j < end; j++) {
            int2 cw = g_cw[j];
            float wt = __int_as_float(cw.y);
            float2 v = __half22float2(eb[(bb + cw.x) * 32 + lane]);
            px0 = fmaf(wt, v.x, px0); py0 = fmaf(wt, v.y, py0);
        }
        float px = px0 + px1, py = py0 + py1;
        shpe[wg][lane * 2] = px; shpe[wg][lane * 2 + 1] = py;
        __syncwarp();
        float tx = 0.0f, ty = 0.0f;
#pragma unroll 8
        for (int i = 0; i < 64; i++) {
            float a = shpe[wg][i];
            float2 g2 = reinterpret_cast<const float2*>(g_G)[i * 32 + lane];
            tx = fmaf(a, g2.x, tx); ty = fmaf(a, g2.y, ty);
        }
        float2 gv = reinterpret_cast<const float2*>(g_v)[lane];
        float partial = (tx + gv.x) * px + (ty + gv.y) * py;
#pragma unroll
        for (int of = 16; of > 0; of >>= 1) partial += __shfl_down_sync(~0u, partial, of);
        if (lane == 0) atomicAdd(&g_acc[1 + b], partial + g_s0);
        float a32 = 0.0f;
#pragma unroll 8
        for (int k = 0; k < 64; k++)
            a32 = fmaf(shpe[wg][k], g_we32[k * 32 + lane], a32);
        g_the[(size_t)w * 32 + lane] = a32;
    }
}

// ========== K5: t = thx + the + bewc (elementwise) ==========
__global__ void tassemble_kernel() {
    int i = blockIdx.x * 1024 + threadIdx.x;
    int row = i >> 5, c = i & 31;
    int n = row & (NNODES - 1);
    g_t[i] = g_thx[n * 32 + c] + g_the[i] + g_bewc[c];
}

// ========== K6: mu/sig = P(t) + bias, fused z ==========
__global__ void prop32z_kernel(const float* __restrict__ bmu, const float* __restrict__ bsig,
                               const float* __restrict__ eps, float* __restrict__ out) {
    int warp = (blockIdx.x * blockDim.x + threadIdx.x) >> 5;
    int lane = threadIdx.x & 31;
    int b = warp >> 12, n = warp & (NNODES - 1);
    const float* tb = g_t + (size_t)b * NNODES * 32;
    float d = g_dinv[n];
    float acc0 = tb[(size_t)n * 32 + lane] * d * d;
    float acc1 = 0.0f;
    int start = g_rowptr[n], end = g_rowptr[n + 1];
    int j = start;
    for (; j + 4 <= end; j += 4) {
        int2 cA = g_cw[j], cB = g_cw[j + 1], cC = g_cw[j + 2], cD = g_cw[j + 3];
        float vA = tb[(size_t)cA.x * 32 + lane];
        float vB = tb[(size_t)cB.x * 32 + lane];
        float vC = tb[(size_t)cC.x * 32 + lane];
        float vD = tb[(size_t)cD.x * 32 + lane];
        acc0 = fmaf(__int_as_float(cA.y), vA, acc0);
        acc1 = fmaf(__int_as_float(cB.y), vB, acc1);
        acc0 = fmaf(__int_as_float(cC.y), vC, acc0);
        acc1 = fmaf(__int_as_float(cD.y), vD, acc1);
    }
    for (; j < end; j++) {
        int2 cw = g_cw[j];
        acc0 = fmaf(__int_as_float(cw.y), tb[(size_t)cw.x * 32 + lane], acc0);
    }
    float acc = acc0 + acc1;
    float biased = acc + ((lane < 16) ? bmu[lane] : bsig[lane - 16]);
    size_t base = ((size_t)b * NNODES + n) * OUTD;
    if (lane < 16) out[OFF_MU + base + lane] = biased;
    else           out[OFF_SIG + base + (lane - 16)] = biased;
    if (b >= 2) {
        float sig = __shfl_sync(~0u, biased, lane + 16);
        if (lane < 16) {
            size_t zi = ((size_t)(b - 2) * NNODES + n) * OUTD + lane;
            float e = eps[zi];
            float zv = fmaf(e, __expf(0.5f * sig), biased);
            out[OFF_Z + zi] = zv;
            out[OFF_ZS + zi] = zv;
            out[OFF_EPS + zi] = e;
        }
    }
}

// ========== K7: adj = sigmoid(z z^T) + snr/rk tail ==========
__device__ __forceinline__ float sigmoid1(float x) {
    float e = __expf(-x);
    float d = 1.0f + e;
    float r; asm("rcp.approx.f32 %0, %1;" : "=f"(r) : "f"(d));
    return r;
}

__global__ __launch_bounds__(256) void adj_kernel(const float* __restrict__ rk_lgt,
                                                  float* __restrict__ out) {
    int tid = threadIdx.x;
    if (blockIdx.x == 0 && blockIdx.y == 0 && blockIdx.z == 0 && tid < 32) {
        if (tid < 5) out[OFF_SNR + tid] = g_acc[0] / g_acc[1 + tid];
        if (tid < 16) out[OFF_RK + tid] = sqrtf(1.0f / (1.0f + expf(-rk_lgt[tid])));
    }
    const float* zb = out + OFF_Z + (size_t)blockIdx.z * NNODES * OUTD;
    float* ab = out + OFF_ADJ + (size_t)blockIdx.z * NNODES * NNODES;
    __shared__ float ziT[16][132];
    __shared__ float zjT[16][132];
    int i0 = blockIdx.y * 128, j0 = blockIdx.x * 128;
#pragma unroll
    for (int rnd = 0; rnd < 2; rnd++) {
        int L4 = tid + rnd * 256;
        float4 a = *reinterpret_cast<const float4*>(zb + (size_t)i0 * 16 + L4 * 4);
        float4 b = *reinterpret_cast<const float4*>(zb + (size_t)j0 * 16 + L4 * 4);
        int r = L4 >> 2, k0 = (L4 & 3) * 4;
        ziT[k0 + 0][r] = a.x; ziT[k0 + 1][r] = a.y; ziT[k0 + 2][r] = a.z; ziT[k0 + 3][r] = a.w;
        zjT[k0 + 0][r] = b.x; zjT[k0 + 1][r] = b.y; zjT[k0 + 2][r] = b.z; zjT[k0 + 3][r] = b.w;
    }
    __syncthreads();
    int tx = tid & 15, ty = tid >> 4;
    u64 acc2[8][4] = {};
#pragma unroll
    for (int k = 0; k < 16; k++) {
        float4 b0 = *reinterpret_cast<const float4*>(&zjT[k][tx * 8]);
        float4 b1 = *reinterpret_cast<const float4*>(&zjT[k][tx * 8 + 4]);
        u64 b2[4];
        b2[0] = pack2(b0.x, b0.y); b2[1] = pack2(b0.z, b0.w);
        b2[2] = pack2(b1.x, b1.y); b2[3] = pack2(b1.z, b1.w);
        float4 a0 = *reinterpret_cast<const float4*>(&ziT[k][ty * 8]);
        float4 a1 = *reinterpret_cast<const float4*>(&ziT[k][ty * 8 + 4]);
        float av[8] = {a0.x, a0.y, a0.z, a0.w, a1.x, a1.y, a1.z, a1.w};
#pragma unroll
        for (int i = 0; i < 8; i++) {
            u64 a2 = pack2(av[i], av[i]);
#pragma unroll
            for (int p = 0; p < 4; p++) acc2[i][p] = fma2(a2, b2[p], acc2[i][p]);
        }
    }
#pragma unroll
    for (int i = 0; i < 8; i++) {
        float v[8];
#pragma unroll
        for (int p = 0; p < 4; p++) unpack2f(acc2[i][p], v[2 * p], v[2 * p + 1]);
        float4 o0, o1;
        o0.x = sigmoid1(v[0]); o0.y = sigmoid1(v[1]); o0.z = sigmoid1(v[2]); o0.w = sigmoid1(v[3]);
        o1.x = sigmoid1(v[4]); o1.y = sigmoid1(v[5]); o1.z = sigmoid1(v[6]); o1.w = sigmoid1(v[7]);
        float* row = ab + (size_t)(i0 + ty * 8 + i) * NNODES + j0 + tx * 8;
        *reinterpret_cast<float4*>(row) = o0;
        *reinterpret_cast<float4*>(row + 4) = o1;
    }
}

// =================================================================================
extern "C" void kernel_launch(void* const* d_in, const int* in_sizes, int n_in,
                              void* d_out, int out_size) {
    (void)in_sizes; (void)n_in; (void)out_size;
    const float* x       = (const float*)d_in[0];
    const int*   ei      = (const int*)d_in[1];
    const float* e_noise = (const float*)d_in[2];
    const float* eps     = (const float*)d_in[3];
    const float* W1      = (const float*)d_in[4];
    const float* b1      = (const float*)d_in[5];
    const float* We      = (const float*)d_in[6];
    const float* be      = (const float*)d_in[7];
    const float* Wmu     = (const float*)d_in[8];
    const float* bmu     = (const float*)d_in[9];
    const float* Wsig    = (const float*)d_in[10];
    const float* bsig    = (const float*)d_in[11];
    const float* rk_lgt  = (const float*)d_in[12];
    float* out = (float*)d_out;

    phase1_kernel<<<651 + 1280, 256>>>(ei, x, W1, e_noise, We, be, Wmu, Wsig);
    dinv_scan_kernel<<<1, 1024>>>();
    csr_fill_kernel<<<512, 256>>>(ei);
    phase4_kernel<<<1024 + 2560, 256>>>(b1, Wmu, Wsig);
    tassemble_kernel<<<NB_E * NNODES * 32 / 1024, 1024>>>();
    prop32z_kernel<<<2560, 256>>>(bmu, bsig, eps, out);
    adj_kernel<<<dim3(32, 32, NB_Z), 256>>>(rk_lgt, out);
}

// round 14
// speedup vs baseline: 1.1974x; 1.0214x over previous
#include <cuda_runtime.h>
#include <cuda_fp16.h>
#include <cstdint>

#define NNODES 4096
#define NEDGES 131072
#define IN_CH 512
#define E_CH 64
#define HID 256
#define OUTD 16
#define NB_E 5
#define NB_Z 3
#define REWEIGHT 0.6454972243679028f

typedef unsigned long long u64;

__device__ int   g_deg[NNODES];
__device__ int   g_rowptr[NNODES + 1];
__device__ int   g_cursor[NNODES];
__device__ float g_dinv[NNODES];
__device__ int2  g_cw[NEDGES];                         // {col, float_bits(w)}
__device__ __align__(16) __half g_h1[NNODES * HID];    // x@W1 (fp16 gather table)
__device__ __align__(16) __half g_e16[NB_E * NNODES * E_CH];  // e_noise fp16
__device__ float g_we32[E_CH * 32];                    // R * We @ [Wmu|Wsig]
__device__ float g_bewc[32];
__device__ float g_G[E_CH * E_CH];                     // R^2 * We We^T
__device__ float g_v[E_CH];                            // 2R * We @ be
__device__ float g_s0;
__device__ float g_the[NB_E * NNODES * 32];
__device__ float g_thx[NNODES * 32];
__device__ float g_t[NB_E * NNODES * 32];
__device__ float g_acc[8];

#define OFF_ADJ 0ull
#define OFF_MU  (OFF_ADJ + 3ull * NNODES * NNODES)
#define OFF_SIG (OFF_MU  + (u64)NB_E * NNODES * OUTD)
#define OFF_Z   (OFF_SIG + (u64)NB_E * NNODES * OUTD)
#define OFF_ZS  (OFF_Z   + (u64)NB_Z * NNODES * OUTD)
#define OFF_EPS (OFF_ZS  + (u64)NB_Z * NNODES * OUTD)
#define OFF_RK  (OFF_EPS + (u64)NB_Z * NNODES * OUTD)
#define OFF_SNR (OFF_RK + 16ull)

// ---------- f32x2 helpers ----------
__device__ __forceinline__ u64 pack2(float a, float b) {
    u64 r; asm("mov.b64 %0, {%1, %2};" : "=l"(r) : "r"(__float_as_int(a)), "r"(__float_as_int(b))); return r;
}
__device__ __forceinline__ void unpack2f(u64 v, float& a, float& b) {
    int x, y; asm("mov.b64 {%0, %1}, %2;" : "=r"(x), "=r"(y) : "l"(v));
    a = __int_as_float(x); b = __int_as_float(y);
}
__device__ __forceinline__ u64 fma2(u64 a, u64 b, u64 c) {
    u64 d; asm("fma.rn.f32x2 %0, %1, %2, %3;" : "=l"(d) : "l"(a), "l"(b), "l"(c)); return d;
}
__device__ __forceinline__ float4 h4_to_f4(uint2 u) {
    __half2 a = *reinterpret_cast<__half2*>(&u.x);
    __half2 b = *reinterpret_cast<__half2*>(&u.y);
    float2 fa = __half22float2(a), fb = __half22float2(b);
    float4 r; r.x = fa.x; r.y = fa.y; r.z = fb.x; r.w = fb.y; return r;
}

// ---------- edge access (inline int64 detection) ----------
__device__ __forceinline__ int detect_w64(const int* __restrict__ ei) {
    return (ei[1] | ei[3] | ei[5] | ei[7] | ei[9] | ei[11] | ei[13] | ei[15]) == 0;
}
__device__ __forceinline__ int edge_src(const int* ei, int i, int w64) { return w64 ? ei[2 * i] : ei[i]; }
__device__ __forceinline__ int edge_dst(const int* ei, int i, int w64) { return w64 ? ei[2 * (NEDGES + i)] : ei[NEDGES + i]; }

// ---------- sgemm body (64x128 tile, BK=16, f32x2) -> g_h1 (fp16) ----------
__device__ __forceinline__ void sgemm_body(const float* __restrict__ A, const float* __restrict__ B,
                                           int K, int bxx, int by, float* pool) {
    float (*As)[65]  = reinterpret_cast<float(*)[65]>(pool);
    float (*Bs)[128] = reinterpret_cast<float(*)[128]>(pool + 16 * 65);
    int tid = threadIdx.x;
    const float* Ab = A + (size_t)by * 64 * K;
    const float* Bb = B + bxx * 128;
    int aRow = tid >> 2, aCol = (tid & 3) * 4;
    int bRow = tid >> 5, bCol = (tid & 31) * 4;
    int ty = tid >> 4, tx = tid & 15;
    u64 acc2[4][4] = {};
    for (int k0 = 0; k0 < K; k0 += 16) {
        float4 a4 = *reinterpret_cast<const float4*>(Ab + (size_t)aRow * K + k0 + aCol);
        float4 b4a = *reinterpret_cast<const float4*>(Bb + (size_t)(k0 + bRow) * HID + bCol);
        float4 b4b = *reinterpret_cast<const float4*>(Bb + (size_t)(k0 + bRow + 8) * HID + bCol);
        __syncthreads();
        As[aCol + 0][aRow] = a4.x; As[aCol + 1][aRow] = a4.y;
        As[aCol + 2][aRow] = a4.z; As[aCol + 3][aRow] = a4.w;
        *reinterpret_cast<float4*>(&Bs[bRow][bCol]) = b4a;
        *reinterpret_cast<float4*>(&Bs[bRow + 8][bCol]) = b4b;
        __syncthreads();
#pragma unroll
        for (int kk = 0; kk < 16; kk++) {
            u64 b2[4];
#pragma unroll
            for (int p = 0; p < 4; p++) b2[p] = reinterpret_cast<const u64*>(&Bs[kk][tx * 8])[p];
#pragma unroll
            for (int i = 0; i < 4; i++) {
                float a = As[kk][ty * 4 + i];
                u64 a2 = pack2(a, a);
#pragma unroll
                for (int p = 0; p < 4; p++) acc2[i][p] = fma2(a2, b2[p], acc2[i][p]);
            }
        }
    }
#pragma unroll
    for (int i = 0; i < 4; i++) {
        size_t row = (size_t)by * 64 + ty * 4 + i;
        int col = bxx * 128 + tx * 8;
        float v[8];
#pragma unroll
        for (int p = 0; p < 4; p++) unpack2f(acc2[i][p], v[2 * p], v[2 * p + 1]);
        __half2 h[4];
#pragma unroll
        for (int p = 0; p < 4; p++) h[p] = __floats2half2_rn(v[2 * p], v[2 * p + 1]);
        uint4 o;
        o.x = *reinterpret_cast<unsigned*>(&h[0]); o.y = *reinterpret_cast<unsigned*>(&h[1]);
        o.z = *reinterpret_cast<unsigned*>(&h[2]); o.w = *reinterpret_cast<unsigned*>(&h[3]);
        *reinterpret_cast<uint4*>(&g_h1[row * HID + col]) = o;
    }
}

// ========== K1: sgemm0 FIRST | deg_count | we32/bewc | G | v,s0 | e-pack ==========
__global__ __launch_bounds__(256) void phase1_kernel(const int* __restrict__ ei,
                                                     const float* __restrict__ x,
                                                     const float* __restrict__ W1,
                                                     const float* __restrict__ e_noise,
                                                     const float* __restrict__ We,
                                                     const float* __restrict__ be,
                                                     const float* __restrict__ Wmu,
                                                     const float* __restrict__ Wsig) {
    __shared__ float pool[16 * 65 + 16 * 128];
    __shared__ float tile[64][33];
    int bx = blockIdx.x, tid = threadIdx.x;
    if (bx < 128) {
        sgemm_body(x, W1, IN_CH, bx & 1, bx >> 1, pool);
    } else if (bx < 640) {
        int w64 = detect_w64(ei);
        int i = (bx - 128) * 256 + tid;
        atomicAdd(&g_deg[edge_dst(ei, i, w64)], 1);
    } else if (bx < 648) {
        int idx = (bx - 640) * 256 + tid;
        int i = idx >> 5, j = idx & 31;
        const float* W = (j < 16) ? Wmu : Wsig;
        int jj = j & 15;
        float acc = 0.0f;
#pragma unroll 8
        for (int k = 0; k < HID; k++) acc = fmaf(We[i * HID + k], W[k * 16 + jj], acc);
        g_we32[i * 32 + j] = acc * REWEIGHT;
    } else if (bx == 648) {
        if (tid < 32) {
            const float* W = (tid < 16) ? Wmu : Wsig;
            int jj = tid & 15;
            float acc = 0.0f;
            for (int k = 0; k < HID; k++) acc = fmaf(be[k], W[k * 16 + jj], acc);
            g_bewc[tid] = acc;
        }
    } else if (bx == 649) {
        float acc[4][4] = {};
        int i0 = (tid >> 4) * 4, j0 = (tid & 15) * 4;
        for (int k0 = 0; k0 < HID; k0 += 32) {
            __syncthreads();
            for (int l = tid; l < 2048; l += 256) {
                int r = l >> 5, kk = l & 31;
                tile[r][kk] = We[r * HID + k0 + kk];
            }
            __syncthreads();
#pragma unroll
            for (int kk = 0; kk < 32; kk++) {
                float a[4], b[4];
#pragma unroll
                for (int ii = 0; ii < 4; ii++) a[ii] = tile[i0 + ii][kk];
#pragma unroll
                for (int jj = 0; jj < 4; jj++) b[jj] = tile[j0 + jj][kk];
#pragma unroll
                for (int ii = 0; ii < 4; ii++)
#pragma unroll
                    for (int jj = 0; jj < 4; jj++) acc[ii][jj] = fmaf(a[ii], b[jj], acc[ii][jj]);
            }
        }
        const float R2 = REWEIGHT * REWEIGHT;
#pragma unroll
        for (int ii = 0; ii < 4; ii++)
#pragma unroll
            for (int jj = 0; jj < 4; jj++) g_G[(i0 + ii) * 64 + j0 + jj] = acc[ii][jj] * R2;
    } else if (bx == 650) {
        if (tid < 64) {
            float a = 0.0f;
            for (int c = 0; c < HID; c++) a = fmaf(We[tid * HID + c], be[c], a);
            g_v[tid] = 2.0f * REWEIGHT * a;
        } else if (tid == 64) {
            float s = 0.0f;
            for (int c = 0; c < HID; c++) s = fmaf(be[c], be[c], s);
            g_s0 = s;
        }
    } else {
        int i = (bx - 651) * 256 + tid;                 // [0, 327680)
        float4 v = reinterpret_cast<const float4*>(e_noise)[i];
        __half2 h0 = __floats2half2_rn(v.x, v.y);
        __half2 h1 = __floats2half2_rn(v.z, v.w);
        uint2 o;
        o.x = *reinterpret_cast<unsigned*>(&h0);
        o.y = *reinterpret_cast<unsigned*>(&h1);
        reinterpret_cast<uint2*>(g_e16)[i] = o;
    }
}

// ========== K2: dinv + scan + g_acc zero ==========
__global__ void dinv_scan_kernel() {
    __shared__ int sums[32];
    int tid = threadIdx.x, base = tid * 4;
    if (tid < 8) g_acc[tid] = 0.0f;
    int v[4], s = 0;
#pragma unroll
    for (int i = 0; i < 4; i++) {
        v[i] = g_deg[base + i];
        g_dinv[base + i] = rsqrtf((float)v[i] + 1.0f);
        s += v[i];
    }
    int lane = tid & 31, wid = tid >> 5, ss = s;
#pragma unroll
    for (int o = 1; o < 32; o <<= 1) { int t = __shfl_up_sync(~0u, ss, o); if (lane >= o) ss += t; }
    if (lane == 31) sums[wid] = ss;
    __syncthreads();
    if (wid == 0) {
        int w = sums[lane];
#pragma unroll
        for (int o = 1; o < 32; o <<= 1) { int t = __shfl_up_sync(~0u, w, o); if (lane >= o) w += t; }
        sums[lane] = w;
    }
    __syncthreads();
    int run = ss - s + (wid > 0 ? sums[wid - 1] : 0);
#pragma unroll
    for (int i = 0; i < 4; i++) { g_rowptr[base + i] = run; g_cursor[base + i] = run; run += v[i]; }
    if (tid == 1023) g_rowptr[NNODES] = run;
}

// ========== K3: csr_fill (packed cw) + deg re-zero ==========
__global__ __launch_bounds__(256) void csr_fill_kernel(const int* __restrict__ ei) {
    int i = blockIdx.x * 256 + threadIdx.x;
    int w64 = detect_w64(ei);
    int s = edge_src(ei, i, w64), d = edge_dst(ei, i, w64);
    int pos = atomicAdd(&g_cursor[d], 1);
    int2 cw; cw.x = s; cw.y = __float_as_int(g_dinv[s] * g_dinv[d]);
    g_cw[pos] = cw;
    if (i < NNODES) g_deg[i] = 0;
}

// ========== K4: prop256x (desc staged) | propE64 (desc staged) ==========
__global__ __launch_bounds__(256) void phase4_kernel(const float* __restrict__ b1,
                                                     const float* __restrict__ Wmu,
                                                     const float* __restrict__ Wsig) {
    __shared__ float sh[4][256];
    __shared__ float red[4][2][32];
    __shared__ float ws[8];
    __shared__ float shpe[8][64];
    __shared__ int2 sdesc[8][32];
    int bx = blockIdx.x, tid = threadIdx.x;
    int w = tid >> 5, lane = tid & 31;
    if (bx < 1024) {
        int g = tid >> 6;                  // node within block (0..3)
        int t = tid & 63;                  // channel-quad id (4 ch per thread)
        int n = bx * 4 + g;
        const uint2* hb = reinterpret_cast<const uint2*>(g_h1);  // 64 uint2 per row
        int start = g_rowptr[n], end = g_rowptr[n + 1];
        float d = g_dinv[n];
        float4 sv = h4_to_f4(hb[n * 64 + t]);
        float a0 = sv.x * d * d, a1 = sv.y * d * d, a2 = sv.z * d * d, a3 = sv.w * d * d;
        float b0 = 0.0f, b1r = 0.0f, b2 = 0.0f, b3 = 0.0f;
        for (int tile = start; tile < end; tile += 32) {
            int m = end - tile; if (m > 32) m = 32;
            __syncwarp();
            if (lane < m) sdesc[w][lane] = g_cw[tile + lane];
            __syncwarp();
            int jj = 0;
            for (; jj + 4 <= m; jj += 4) {
                int2 cA = sdesc[w][jj], cB = sdesc[w][jj + 1];
                int2 cC = sdesc[w][jj + 2], cD = sdesc[w][jj + 3];
                uint2 uA = hb[cA.x * 64 + t];
                uint2 uB = hb[cB.x * 64 + t];
                uint2 uC = hb[cC.x * 64 + t];
                uint2 uD = hb[cD.x * 64 + t];
                float4 vA = h4_to_f4(uA), vB = h4_to_f4(uB), vC = h4_to_f4(uC), vD = h4_to_f4(uD);
                float wA = __int_as_float(cA.y), wB = __int_as_float(cB.y);
                float wC = __int_as_float(cC.y), wD = __int_as_float(cD.y);
                a0 = fmaf(wA, vA.x, a0); a1 = fmaf(wA, vA.y, a1); a2 = fmaf(wA, vA.z, a2); a3 = fmaf(wA, vA.w, a3);
                b0 = fmaf(wB, vB.x, b0); b1r = fmaf(wB, vB.y, b1r); b2 = fmaf(wB, vB.z, b2); b3 = fmaf(wB, vB.w, b3);
                a0 = fmaf(wC, vC.x, a0); a1 = fmaf(wC, vC.y, a1); a2 = fmaf(wC, vC.z, a2); a3 = fmaf(wC, vC.w, a3);
                b0 = fmaf(wD, vD.x, b0); b1r = fmaf(wD, vD.y, b1r); b2 = fmaf(wD, vD.z, b2); b3 = fmaf(wD, vD.w, b3);
            }
            for (; jj < m; jj++) {
                int2 cw = sdesc[w][jj];
                float wt = __int_as_float(cw.y);
                float4 v = h4_to_f4(hb[cw.x * 64 + t]);
                a0 = fmaf(wt, v.x, a0); a1 = fmaf(wt, v.y, a1); a2 = fmaf(wt, v.z, a2); a3 = fmaf(wt, v.w, a3);
            }
        }
        float4 bb = reinterpret_cast<const float4*>(b1)[t];
        float4 hv;
        hv.x = fmaxf(a0 + b0 + bb.x, 0.0f);
        hv.y = fmaxf(a1 + b1r + bb.y, 0.0f);
        hv.z = fmaxf(a2 + b2 + bb.z, 0.0f);
        hv.w = fmaxf(a3 + b3 + bb.w, 0.0f);
        reinterpret_cast<float4*>(sh[g])[t] = hv;
        float s = hv.x * hv.x + hv.y * hv.y + hv.z * hv.z + hv.w * hv.w;
#pragma unroll
        for (int of = 16; of > 0; of >>= 1) s += __shfl_down_sync(~0u, s, of);
        if (lane == 0) ws[w] = s;
        __syncthreads();
        if (tid == 0) {
            float tot = ws[0] + ws[1] + ws[2] + ws[3] + ws[4] + ws[5] + ws[6] + ws[7];
            atomicAdd(&g_acc[0], tot);
        }
        int seg = t >> 5, c0 = t & 31;
        const float* W = (c0 < 16) ? Wmu : Wsig;
        int cc = c0 & 15;
        float tt = 0.0f;
        int k0 = seg * 128;
#pragma unroll 16
        for (int k = k0; k < k0 + 128; k++) tt = fmaf(sh[g][k], W[k * 16 + cc], tt);
        red[g][seg][c0] = tt;
        __syncthreads();
        if (t < 32) g_thx[n * 32 + t] = red[g][0][t] + red[g][1][t];
    } else {
        int wk = (bx - 1024) * 8 + w;      // (b,n) per warp
        int b = wk >> 12, n = wk & (NNODES - 1);
        const __half2* eb = reinterpret_cast<const __half2*>(g_e16);
        int start = g_rowptr[n], end = g_rowptr[n + 1];
        float d = g_dinv[n];
        size_t bb = (size_t)b * NNODES;
        float2 self = __half22float2(eb[(bb + n) * 32 + lane]);
        float px0 = self.x * d * d, py0 = self.y * d * d;
        float px1 = 0.0f, py1 = 0.0f;
        for (int tile = start; tile < end; tile += 32) {
            int m = end - tile; if (m > 32) m = 32;
            __syncwarp();
            if (lane < m) sdesc[w][lane] = g_cw[tile + lane];
            __syncwarp();
            int jj = 0;
            for (; jj + 4 <= m; jj += 4) {
                int2 cA = sdesc[w][jj], cB = sdesc[w][jj + 1];
                int2 cC = sdesc[w][jj + 2], cD = sdesc[w][jj + 3];
                __half2 hA = eb[(bb + cA.x) * 32 + lane];
                __half2 hB = eb[(bb + cB.x) * 32 + lane];
                __half2 hC = eb[(bb + cC.x) * 32 + lane];
                __half2 hD = eb[(bb + cD.x) * 32 + lane];
                float2 vA = __half22float2(hA), vB = __half22float2(hB);
                float2 vC = __half22float2(hC), vD = __half22float2(hD);
                float wA = __int_as_float(cA.y), wB = __int_as_float(cB.y);
                float wC = __int_as_float(cC.y), wD = __int_as_float(cD.y);
                px0 = fmaf(wA, vA.x, px0); py0 = fmaf(wA, vA.y, py0);
                px1 = fmaf(wB, vB.x, px1); py1 = fmaf(wB, vB.y, py1);
                px0 = fmaf(wC, vC.x, px0); py0 = fmaf(wC, vC.y, py0);
                px1 = fmaf(wD, vD.x, px1); py1 = fmaf(wD, vD.y, py1);
            }
            for (; jj < m; jj++) {
                int2 cw = sdesc[w][jj];
                float wt = __int_as_float(cw.y);
                float2 v = __half22float2(eb[(bb + cw.x) * 32 + lane]);
                px0 = fmaf(wt, v.x, px0); py0 = fmaf(wt, v.y, py0);
            }
        }
        float px = px0 + px1, py = py0 + py1;
        shpe[w][lane * 2] = px; shpe[w][lane * 2 + 1] = py;
        __syncwarp();
        float tx = 0.0f, ty = 0.0f;
#pragma unroll 8
        for (int i = 0; i < 64; i++) {
            float a = shpe[w][i];
            float2 g2 = reinterpret_cast<const float2*>(g_G)[i * 32 + lane];
            tx = fmaf(a, g2.x, tx); ty = fmaf(a, g2.y, ty);
        }
        float2 gv = reinterpret_cast<const float2*>(g_v)[lane];
        float partial = (tx + gv.x) * px + (ty + gv.y) * py;
#pragma unroll
        for (int of = 16; of > 0; of >>= 1) partial += __shfl_down_sync(~0u, partial, of);
        if (lane == 0) atomicAdd(&g_acc[1 + b], partial + g_s0);
        float a32 = 0.0f;
#pragma unroll 8
        for (int k = 0; k < 64; k++)
            a32 = fmaf(shpe[w][k], g_we32[k * 32 + lane], a32);
        g_the[(size_t)wk * 32 + lane] = a32;
    }
}

// ========== K5: t = thx + the + bewc (elementwise) ==========
__global__ void tassemble_kernel() {
    int i = blockIdx.x * 1024 + threadIdx.x;
    int row = i >> 5, c = i & 31;
    int n = row & (NNODES - 1);
    g_t[i] = g_thx[n * 32 + c] + g_the[i] + g_bewc[c];
}

// ========== K6: mu/sig = P(t) + bias, fused z (desc staged) ==========
__global__ __launch_bounds__(256) void prop32z_kernel(const float* __restrict__ bmu,
                                                      const float* __restrict__ bsig,
                                                      const float* __restrict__ eps,
                                                      float* __restrict__ out) {
    __shared__ int2 sdesc[8][32];
    int w = threadIdx.x >> 5, lane = threadIdx.x & 31;
    int warp = blockIdx.x * 8 + w;
    int b = warp >> 12, n = warp & (NNODES - 1);
    const float* tb = g_t + (size_t)b * NNODES * 32;
    float d = g_dinv[n];
    float acc0 = tb[(size_t)n * 32 + lane] * d * d;
    float acc1 = 0.0f;
    int start = g_rowptr[n], end = g_rowptr[n + 1];
    for (int tile = start; tile < end; tile += 32) {
        int m = end - tile; if (m > 32) m = 32;
        __syncwarp();
        if (lane < m) sdesc[w][lane] = g_cw[tile + lane];
        __syncwarp();
        int jj = 0;
        for (; jj + 4 <= m; jj += 4) {
            int2 cA = sdesc[w][jj], cB = sdesc[w][jj + 1];
            int2 cC = sdesc[w][jj + 2], cD = sdesc[w][jj + 3];
            float vA = tb[(size_t)cA.x * 32 + lane];
            float vB = tb[(size_t)cB.x * 32 + lane];
            float vC = tb[(size_t)cC.x * 32 + lane];
            float vD = tb[(size_t)cD.x * 32 + lane];
            acc0 = fmaf(__int_as_float(cA.y), vA, acc0);
            acc1 = fmaf(__int_as_float(cB.y), vB, acc1);
            acc0 = fmaf(__int_as_float(cC.y), vC, acc0);
            acc1 = fmaf(__int_as_float(cD.y), vD, acc1);
        }
        for (; jj < m; jj++) {
            int2 cw = sdesc[w][jj];
            acc0 = fmaf(__int_as_float(cw.y), tb[(size_t)cw.x * 32 + lane], acc0);
        }
    }
    float acc = acc0 + acc1;
    float biased = acc + ((lane < 16) ? bmu[lane] : bsig[lane - 16]);
    size_t base = ((size_t)b * NNODES + n) * OUTD;
    if (lane < 16) out[OFF_MU + base + lane] = biased;
    else           out[OFF_SIG + base + (lane - 16)] = biased;
    if (b >= 2) {
        float sig = __shfl_sync(~0u, biased, lane + 16);
        if (lane < 16) {
            size_t zi = ((size_t)(b - 2) * NNODES + n) * OUTD + lane;
            float e = eps[zi];
            float zv = fmaf(e, __expf(0.5f * sig), biased);
            out[OFF_Z + zi] = zv;
            out[OFF_ZS + zi] = zv;
            out[OFF_EPS + zi] = e;
        }
    }
}

// ========== K7: adj = sigmoid(z z^T) + snr/rk tail ==========
__device__ __forceinline__ float sigmoid1(float x) {
    float e = __expf(-x);
    float d = 1.0f + e;
    float r; asm("rcp.approx.f32 %0, %1;" : "=f"(r) : "f"(d));
    return r;
}

__global__ __launch_bounds__(256) void adj_kernel(const float* __restrict__ rk_lgt,
                                                  float* __restrict__ out) {
    int tid = threadIdx.x;
    if (blockIdx.x == 0 && blockIdx.y == 0 && blockIdx.z == 0 && tid < 32) {
        if (tid < 5) out[OFF_SNR + tid] = g_acc[0] / g_acc[1 + tid];
        if (tid < 16) out[OFF_RK + tid] = sqrtf(1.0f / (1.0f + expf(-rk_lgt[tid])));
    }
    const float* zb = out + OFF_Z + (size_t)blockIdx.z * NNODES * OUTD;
    float* ab = out + OFF_ADJ + (size_t)blockIdx.z * NNODES * NNODES;
    __shared__ float ziT[16][132];
    __shared__ float zjT[16][132];
    int i0 = blockIdx.y * 128, j0 = blockIdx.x * 128;
#pragma unroll
    for (int rnd = 0; rnd < 2; rnd++) {
        int L4 = tid + rnd * 256;
        float4 a = *reinterpret_cast<const float4*>(zb + (size_t)i0 * 16 + L4 * 4);
        float4 b = *reinterpret_cast<const float4*>(zb + (size_t)j0 * 16 + L4 * 4);
        int r = L4 >> 2, k0 = (L4 & 3) * 4;
        ziT[k0 + 0][r] = a.x; ziT[k0 + 1][r] = a.y; ziT[k0 + 2][r] = a.z; ziT[k0 + 3][r] = a.w;
        zjT[k0 + 0][r] = b.x; zjT[k0 + 1][r] = b.y; zjT[k0 + 2][r] = b.z; zjT[k0 + 3][r] = b.w;
    }
    __syncthreads();
    int tx = tid & 15, ty = tid >> 4;
    u64 acc2[8][4] = {};
#pragma unroll
    for (int k = 0; k < 16; k++) {
        float4 b0 = *reinterpret_cast<const float4*>(&zjT[k][tx * 8]);
        float4 b1 = *reinterpret_cast<const float4*>(&zjT[k][tx * 8 + 4]);
        u64 b2[4];
        b2[0] = pack2(b0.x, b0.y); b2[1] = pack2(b0.z, b0.w);
        b2[2] = pack2(b1.x, b1.y); b2[3] = pack2(b1.z, b1.w);
        float4 a0 = *reinterpret_cast<const float4*>(&ziT[k][ty * 8]);
        float4 a1 = *reinterpret_cast<const float4*>(&ziT[k][ty * 8 + 4]);
        float av[8] = {a0.x, a0.y, a0.z, a0.w, a1.x, a1.y, a1.z, a1.w};
#pragma unroll
        for (int i = 0; i < 8; i++) {
            u64 a2 = pack2(av[i], av[i]);
#pragma unroll
            for (int p = 0; p < 4; p++) acc2[i][p] = fma2(a2, b2[p], acc2[i][p]);
        }
    }
#pragma unroll
    for (int i = 0; i < 8; i++) {
        float v[8];
#pragma unroll
        for (int p = 0; p < 4; p++) unpack2f(acc2[i][p], v[2 * p], v[2 * p + 1]);
        float4 o0, o1;
        o0.x = sigmoid1(v[0]); o0.y = sigmoid1(v[1]); o0.z = sigmoid1(v[2]); o0.w = sigmoid1(v[3]);
        o1.x = sigmoid1(v[4]); o1.y = sigmoid1(v[5]); o1.z = sigmoid1(v[6]); o1.w = sigmoid1(v[7]);
        float* row = ab + (size_t)(i0 + ty * 8 + i) * NNODES + j0 + tx * 8;
        *reinterpret_cast<float4*>(row) = o0;
        *reinterpret_cast<float4*>(row + 4) = o1;
    }
}

// =================================================================================
extern "C" void kernel_launch(void* const* d_in, const int* in_sizes, int n_in,
                              void* d_out, int out_size) {
    (void)in_sizes; (void)n_in; (void)out_size;
    const float* x       = (const float*)d_in[0];
    const int*   ei      = (const int*)d_in[1];
    const float* e_noise = (const float*)d_in[2];
    const float* eps     = (const float*)d_in[3];
    const float* W1      = (const float*)d_in[4];
    const float* b1      = (const float*)d_in[5];
    const float* We      = (const float*)d_in[6];
    const float* be      = (const float*)d_in[7];
    const float* Wmu     = (const float*)d_in[8];
    const float* bmu     = (const float*)d_in[9];
    const float* Wsig    = (const float*)d_in[10];
    const float* bsig    = (const float*)d_in[11];
    const float* rk_lgt  = (const float*)d_in[12];
    float* out = (float*)d_out;

    phase1_kernel<<<651 + 1280, 256>>>(ei, x, W1, e_noise, We, be, Wmu, Wsig);
    dinv_scan_kernel<<<1, 1024>>>();
    csr_fill_kernel<<<512, 256>>>(ei);
    phase4_kernel<<<1024 + 2560, 256>>>(b1, Wmu, Wsig);
    tassemble_kernel<<<NB_E * NNODES * 32 / 1024, 1024>>>();
    prop32z_kernel<<<2560, 256>>>(bmu, bsig, eps, out);
    adj_kernel<<<dim3(32, 32, NB_Z), 256>>>(rk_lgt, out);
}